// round 7
// baseline (speedup 1.0000x reference)
#include <cuda_runtime.h>

// e3nn uvu tensor product, HBM-bound streaming kernel.
//   x: (B, 1024) = 256x0e + 256x1o (u-major triplets)
//   y: (B, 4), w: (1280,), out: (B, 1024)
//
// out0[u]   = C0*w0[u]*x0[u]*y0 + C0*C1*w1[u]*dot(x1[u], y1)
// out1[u,k] = C1*w2[u]*x0[u]*y1[k] + C1*w3[u]*y0*x1[u,k] + C2*w4[u]*cross(x1[u],y1)[k]
//
// R6: persistent grid-stride kernel, exact-fit grid (152 SMs x 4 CTAs).
// Weights loaded once per CTA into registers; single wave; R2 hot-loop body.

#define THREADS 256     // 4 row-slices x 64 u-groups
#define GRID    608     // 152 SMs x 4 blocks/SM (GB300)

__global__ __launch_bounds__(THREADS, 4)
void tp_uvu_kernel(const float* __restrict__ x,
                   const float* __restrict__ y,
                   const float* __restrict__ w,
                   float* __restrict__ out,
                   int B)
{
    const int tid = threadIdx.x;
    const int ug  = tid & 63;        // u-group: 4 consecutive u's
    const int zl  = tid >> 6;        // 0..3 row slice
    const int u   = ug << 2;

    const float C0  = 0.70710678118654752f;   // 1/sqrt(2)
    const float C1  = 0.57735026918962576f;   // 1/sqrt(3)
    const float C01 = C0 * C1;
    const float C2  = 0.40824829046386302f;   // 1/sqrt(6)

    // Per-CTA one-time weight load, normalization folded in.
    const float4 w0 = *(const float4*)(w + 0 * 256 + u);
    const float4 w1 = *(const float4*)(w + 1 * 256 + u);
    const float4 w2 = *(const float4*)(w + 2 * 256 + u);
    const float4 w3 = *(const float4*)(w + 3 * 256 + u);
    const float4 w4 = *(const float4*)(w + 4 * 256 + u);

    const float a0[4] = {C0 * w0.x, C0 * w0.y, C0 * w0.z, C0 * w0.w};
    const float a1[4] = {C01 * w1.x, C01 * w1.y, C01 * w1.z, C01 * w1.w};
    const float a2[4] = {C1 * w2.x, C1 * w2.y, C1 * w2.z, C1 * w2.w};
    const float a3[4] = {C1 * w3.x, C1 * w3.y, C1 * w3.z, C1 * w3.w};
    const float a4[4] = {C2 * w4.x, C2 * w4.y, C2 * w4.z, C2 * w4.w};

    const int G = (B + 3) >> 2;      // row-groups of 4 rows

    for (int g = blockIdx.x; g < G; g += gridDim.x) {
        const int z = (g << 2) + zl;
        if (z >= B) continue;        // only possible on the last partial group

        const float* xr   = x   + (size_t)z * 1024;
        float*       orow = out + (size_t)z * 1024;

        // Front-batch independent global loads.
        const float4 yv  = *(const float4*)(y + (size_t)z * 4);
        const float4 x0v = __ldcs((const float4*)(xr + u));
        const float4 xa  = __ldcs((const float4*)(xr + 256 + u * 3));
        const float4 xb  = __ldcs((const float4*)(xr + 256 + u * 3 + 4));
        const float4 xc  = __ldcs((const float4*)(xr + 256 + u * 3 + 8));

        const float y0 = yv.x, e1x = yv.y, e1y = yv.z, e1z = yv.w;

        const float vx[4]  = {xa.x, xa.w, xb.z, xc.y};
        const float vy[4]  = {xa.y, xb.x, xb.w, xc.z};
        const float vz[4]  = {xa.z, xb.y, xc.x, xc.w};
        const float x0s[4] = {x0v.x, x0v.y, x0v.z, x0v.w};

        float o0[4], ox[4], oy[4], oz[4];
        #pragma unroll
        for (int j = 0; j < 4; ++j) {
            const float dot = vx[j] * e1x + vy[j] * e1y + vz[j] * e1z;
            o0[j] = a0[j] * x0s[j] * y0 + a1[j] * dot;

            const float cx = vy[j] * e1z - vz[j] * e1y;
            const float cy = vz[j] * e1x - vx[j] * e1z;
            const float cz = vx[j] * e1y - vy[j] * e1x;

            const float s2 = a2[j] * x0s[j];   // scales y1
            const float s3 = a3[j] * y0;       // scales x1

            ox[j] = s2 * e1x + s3 * vx[j] + a4[j] * cx;
            oy[j] = s2 * e1y + s3 * vy[j] + a4[j] * cy;
            oz[j] = s2 * e1z + s3 * vz[j] + a4[j] * cz;
        }

        __stcs((float4*)(orow + u), make_float4(o0[0], o0[1], o0[2], o0[3]));
        __stcs((float4*)(orow + 256 + u * 3),     make_float4(ox[0], oy[0], oz[0], ox[1]));
        __stcs((float4*)(orow + 256 + u * 3 + 4), make_float4(oy[1], oz[1], ox[2], oy[2]));
        __stcs((float4*)(orow + 256 + u * 3 + 8), make_float4(oz[2], ox[3], oy[3], oz[3]));
    }
}

extern "C" void kernel_launch(void* const* d_in, const int* in_sizes, int n_in,
                              void* d_out, int out_size)
{
    const float* x = (const float*)d_in[0];
    const float* y = (const float*)d_in[1];
    const float* w = (const float*)d_in[2];
    float* out = (float*)d_out;

    const int B = in_sizes[0] / 1024;
    const int G = (B + 3) / 4;
    int grid = GRID;
    if (grid > G) grid = G;
    tp_uvu_kernel<<<grid, THREADS>>>(x, y, w, out, B);
}

// round 8
// speedup vs baseline: 1.2093x; 1.2093x over previous
#include <cuda_runtime.h>

// e3nn uvu tensor product, HBM-bound streaming kernel.
//   x: (B, 1024) = 256x0e + 256x1o (u-major triplets)
//   y: (B, 4), w: (1280,), out: (B, 1024)
//
// out0[u]   = C0*w0[u]*x0[u]*y0 + C0*C1*w1[u]*dot(x1[u], y1)
// out1[u,k] = C1*w2[u]*x0[u]*y1[k] + C1*w3[u]*y0*x1[u,k] + C2*w4[u]*cross(x1[u],y1)[k]
//
// R7: R2 structure (best, 163.5us) with doubled per-block contiguous
// footprint (ZPB=64 -> 256KB sequential per CTA) for DRAM page locality.
// Plain loads/stores (streaming hints measured -1.4% DRAM%).

#define ZPB 64          // batch rows per block (256KB contiguous footprint)
#define THREADS 256     // 4 row-slices x 64 u-groups

__global__ __launch_bounds__(THREADS)
void tp_uvu_kernel(const float* __restrict__ x,
                   const float* __restrict__ y,
                   const float* __restrict__ w,
                   float* __restrict__ out,
                   int B)
{
    const int tid = threadIdx.x;
    const int ug  = tid & 63;        // u-group: 4 consecutive u's
    const int zl  = tid >> 6;        // 0..3 row slice within block
    const int u   = ug << 2;

    const float C0  = 0.70710678118654752f;   // 1/sqrt(2)
    const float C1  = 0.57735026918962576f;   // 1/sqrt(3)
    const float C01 = C0 * C1;
    const float C2  = 0.40824829046386302f;   // 1/sqrt(6)

    // Load per-u weights once, fold path-normalization constants in.
    const float4 w0 = *(const float4*)(w + 0 * 256 + u);
    const float4 w1 = *(const float4*)(w + 1 * 256 + u);
    const float4 w2 = *(const float4*)(w + 2 * 256 + u);
    const float4 w3 = *(const float4*)(w + 3 * 256 + u);
    const float4 w4 = *(const float4*)(w + 4 * 256 + u);

    const float a0[4] = {C0 * w0.x, C0 * w0.y, C0 * w0.z, C0 * w0.w};
    const float a1[4] = {C01 * w1.x, C01 * w1.y, C01 * w1.z, C01 * w1.w};
    const float a2[4] = {C1 * w2.x, C1 * w2.y, C1 * w2.z, C1 * w2.w};
    const float a3[4] = {C1 * w3.x, C1 * w3.y, C1 * w3.z, C1 * w3.w};
    const float a4[4] = {C2 * w4.x, C2 * w4.y, C2 * w4.z, C2 * w4.w};

    const int zbase = blockIdx.x * ZPB + zl;

    #pragma unroll
    for (int it = 0; it < ZPB / 4; ++it) {
        const int z = zbase + it * 4;
        if (z >= B) return;

        const float* xr   = x   + (size_t)z * 1024;
        float*       orow = out + (size_t)z * 1024;

        // Front-batch all independent global loads (max MLP before math).
        const float4 yv  = *(const float4*)(y + (size_t)z * 4);
        const float4 x0v = *(const float4*)(xr + u);
        const float4 xa  = *(const float4*)(xr + 256 + u * 3);
        const float4 xb  = *(const float4*)(xr + 256 + u * 3 + 4);
        const float4 xc  = *(const float4*)(xr + 256 + u * 3 + 8);

        const float y0 = yv.x, e1x = yv.y, e1y = yv.z, e1z = yv.w;

        // unpack x1 vectors for the 4 u's
        const float vx[4]  = {xa.x, xa.w, xb.z, xc.y};
        const float vy[4]  = {xa.y, xb.x, xb.w, xc.z};
        const float vz[4]  = {xa.z, xb.y, xc.x, xc.w};
        const float x0s[4] = {x0v.x, x0v.y, x0v.z, x0v.w};

        float o0[4], ox[4], oy[4], oz[4];
        #pragma unroll
        for (int j = 0; j < 4; ++j) {
            const float dot = vx[j] * e1x + vy[j] * e1y + vz[j] * e1z;
            o0[j] = a0[j] * x0s[j] * y0 + a1[j] * dot;

            const float cx = vy[j] * e1z - vz[j] * e1y;
            const float cy = vz[j] * e1x - vx[j] * e1z;
            const float cz = vx[j] * e1y - vy[j] * e1x;

            const float s2 = a2[j] * x0s[j];   // scales y1
            const float s3 = a3[j] * y0;       // scales x1

            ox[j] = s2 * e1x + s3 * vx[j] + a4[j] * cx;
            oy[j] = s2 * e1y + s3 * vy[j] + a4[j] * cy;
            oz[j] = s2 * e1z + s3 * vz[j] + a4[j] * cz;
        }

        // stores: same layout as input
        *(float4*)(orow + u) = make_float4(o0[0], o0[1], o0[2], o0[3]);
        *(float4*)(orow + 256 + u * 3)     = make_float4(ox[0], oy[0], oz[0], ox[1]);
        *(float4*)(orow + 256 + u * 3 + 4) = make_float4(oy[1], oz[1], ox[2], oy[2]);
        *(float4*)(orow + 256 + u * 3 + 8) = make_float4(oz[2], ox[3], oy[3], oz[3]);
    }
}

extern "C" void kernel_launch(void* const* d_in, const int* in_sizes, int n_in,
                              void* d_out, int out_size)
{
    const float* x = (const float*)d_in[0];
    const float* y = (const float*)d_in[1];
    const float* w = (const float*)d_in[2];
    float* out = (float*)d_out;

    const int B = in_sizes[0] / 1024;
    const int grid = (B + ZPB - 1) / ZPB;
    tp_uvu_kernel<<<grid, THREADS>>>(x, y, w, out, B);
}

// round 9
// speedup vs baseline: 1.3001x; 1.0751x over previous
#include <cuda_runtime.h>

// e3nn uvu tensor product, HBM-bound streaming kernel.
//   x: (B, 1024) = 256x0e + 256x1o (u-major triplets)
//   y: (B, 4), w: (1280,), out: (B, 1024)
//
// out0[u]   = C0*w0[u]*x0[u]*y0 + C0*C1*w1[u]*dot(x1[u], y1)
// out1[u,k] = C1*w2[u]*x0[u]*y1[k] + C1*w3[u]*y0*x1[u,k] + C2*w4[u]*cross(x1[u],y1)[k]
//
// R8: R2 body with FINER work quantum (ZPB=16, 64KB/CTA, grid 8192) to
// shrink the multi-CTA straggler tail (ZPB=64 made it worse; direction is
// finer). Plain loads/stores, weights in registers.

#define ZPB 16          // batch rows per block (64KB contiguous footprint)
#define THREADS 256     // 4 row-slices x 64 u-groups

__global__ __launch_bounds__(THREADS)
void tp_uvu_kernel(const float* __restrict__ x,
                   const float* __restrict__ y,
                   const float* __restrict__ w,
                   float* __restrict__ out,
                   int B)
{
    const int tid = threadIdx.x;
    const int ug  = tid & 63;        // u-group: 4 consecutive u's
    const int zl  = tid >> 6;        // 0..3 row slice within block
    const int u   = ug << 2;

    const float C0  = 0.70710678118654752f;   // 1/sqrt(2)
    const float C1  = 0.57735026918962576f;   // 1/sqrt(3)
    const float C01 = C0 * C1;
    const float C2  = 0.40824829046386302f;   // 1/sqrt(6)

    // Load per-u weights once, fold path-normalization constants in.
    const float4 w0 = *(const float4*)(w + 0 * 256 + u);
    const float4 w1 = *(const float4*)(w + 1 * 256 + u);
    const float4 w2 = *(const float4*)(w + 2 * 256 + u);
    const float4 w3 = *(const float4*)(w + 3 * 256 + u);
    const float4 w4 = *(const float4*)(w + 4 * 256 + u);

    const float a0[4] = {C0 * w0.x, C0 * w0.y, C0 * w0.z, C0 * w0.w};
    const float a1[4] = {C01 * w1.x, C01 * w1.y, C01 * w1.z, C01 * w1.w};
    const float a2[4] = {C1 * w2.x, C1 * w2.y, C1 * w2.z, C1 * w2.w};
    const float a3[4] = {C1 * w3.x, C1 * w3.y, C1 * w3.z, C1 * w3.w};
    const float a4[4] = {C2 * w4.x, C2 * w4.y, C2 * w4.z, C2 * w4.w};

    const int zbase = blockIdx.x * ZPB + zl;

    #pragma unroll
    for (int it = 0; it < ZPB / 4; ++it) {
        const int z = zbase + it * 4;
        if (z >= B) return;

        const float* xr   = x   + (size_t)z * 1024;
        float*       orow = out + (size_t)z * 1024;

        // Front-batch all independent global loads (max MLP before math).
        const float4 yv  = *(const float4*)(y + (size_t)z * 4);
        const float4 x0v = *(const float4*)(xr + u);
        const float4 xa  = *(const float4*)(xr + 256 + u * 3);
        const float4 xb  = *(const float4*)(xr + 256 + u * 3 + 4);
        const float4 xc  = *(const float4*)(xr + 256 + u * 3 + 8);

        const float y0 = yv.x, e1x = yv.y, e1y = yv.z, e1z = yv.w;

        // unpack x1 vectors for the 4 u's
        const float vx[4]  = {xa.x, xa.w, xb.z, xc.y};
        const float vy[4]  = {xa.y, xb.x, xb.w, xc.z};
        const float vz[4]  = {xa.z, xb.y, xc.x, xc.w};
        const float x0s[4] = {x0v.x, x0v.y, x0v.z, x0v.w};

        float o0[4], ox[4], oy[4], oz[4];
        #pragma unroll
        for (int j = 0; j < 4; ++j) {
            const float dot = vx[j] * e1x + vy[j] * e1y + vz[j] * e1z;
            o0[j] = a0[j] * x0s[j] * y0 + a1[j] * dot;

            const float cx = vy[j] * e1z - vz[j] * e1y;
            const float cy = vz[j] * e1x - vx[j] * e1z;
            const float cz = vx[j] * e1y - vy[j] * e1x;

            const float s2 = a2[j] * x0s[j];   // scales y1
            const float s3 = a3[j] * y0;       // scales x1

            ox[j] = s2 * e1x + s3 * vx[j] + a4[j] * cx;
            oy[j] = s2 * e1y + s3 * vy[j] + a4[j] * cy;
            oz[j] = s2 * e1z + s3 * vz[j] + a4[j] * cz;
        }

        // stores: same layout as input
        *(float4*)(orow + u) = make_float4(o0[0], o0[1], o0[2], o0[3]);
        *(float4*)(orow + 256 + u * 3)     = make_float4(ox[0], oy[0], oz[0], ox[1]);
        *(float4*)(orow + 256 + u * 3 + 4) = make_float4(oy[1], oz[1], ox[2], oy[2]);
        *(float4*)(orow + 256 + u * 3 + 8) = make_float4(oz[2], ox[3], oy[3], oz[3]);
    }
}

extern "C" void kernel_launch(void* const* d_in, const int* in_sizes, int n_in,
                              void* d_out, int out_size)
{
    const float* x = (const float*)d_in[0];
    const float* y = (const float*)d_in[1];
    const float* w = (const float*)d_in[2];
    float* out = (float*)d_out;

    const int B = in_sizes[0] / 1024;
    const int grid = (B + ZPB - 1) / ZPB;
    tp_uvu_kernel<<<grid, THREADS>>>(x, y, w, out, B);
}

// round 10
// speedup vs baseline: 1.3175x; 1.0134x over previous
#include <cuda_runtime.h>

// e3nn uvu tensor product, HBM-bound streaming kernel.
//   x: (B, 1024) = 256x0e + 256x1o (u-major triplets)
//   y: (B, 4), w: (1280,), out: (B, 1024)
//
// out0[u]   = C0*w0[u]*x0[u]*y0 + C0*C1*w1[u]*dot(x1[u], y1)
// out1[u,k] = C1*w2[u]*x0[u]*y1[k] + C1*w3[u]*y0*x1[u,k] + C2*w4[u]*cross(x1[u],y1)[k]
//
// R9: quantum sweep continuation. ZPB 64->32->16 monotone improved
// (171.8 -> 163.5 -> 159.8 us); try ZPB=8 (32KB/CTA, grid 16384).

#define ZPB 8           // batch rows per block (32KB contiguous footprint)
#define THREADS 256     // 4 row-slices x 64 u-groups

__global__ __launch_bounds__(THREADS)
void tp_uvu_kernel(const float* __restrict__ x,
                   const float* __restrict__ y,
                   const float* __restrict__ w,
                   float* __restrict__ out,
                   int B)
{
    const int tid = threadIdx.x;
    const int ug  = tid & 63;        // u-group: 4 consecutive u's
    const int zl  = tid >> 6;        // 0..3 row slice within block
    const int u   = ug << 2;

    const float C0  = 0.70710678118654752f;   // 1/sqrt(2)
    const float C1  = 0.57735026918962576f;   // 1/sqrt(3)
    const float C01 = C0 * C1;
    const float C2  = 0.40824829046386302f;   // 1/sqrt(6)

    // Load per-u weights once, fold path-normalization constants in.
    const float4 w0 = *(const float4*)(w + 0 * 256 + u);
    const float4 w1 = *(const float4*)(w + 1 * 256 + u);
    const float4 w2 = *(const float4*)(w + 2 * 256 + u);
    const float4 w3 = *(const float4*)(w + 3 * 256 + u);
    const float4 w4 = *(const float4*)(w + 4 * 256 + u);

    const float a0[4] = {C0 * w0.x, C0 * w0.y, C0 * w0.z, C0 * w0.w};
    const float a1[4] = {C01 * w1.x, C01 * w1.y, C01 * w1.z, C01 * w1.w};
    const float a2[4] = {C1 * w2.x, C1 * w2.y, C1 * w2.z, C1 * w2.w};
    const float a3[4] = {C1 * w3.x, C1 * w3.y, C1 * w3.z, C1 * w3.w};
    const float a4[4] = {C2 * w4.x, C2 * w4.y, C2 * w4.z, C2 * w4.w};

    const int zbase = blockIdx.x * ZPB + zl;

    #pragma unroll
    for (int it = 0; it < ZPB / 4; ++it) {
        const int z = zbase + it * 4;
        if (z >= B) return;

        const float* xr   = x   + (size_t)z * 1024;
        float*       orow = out + (size_t)z * 1024;

        // Front-batch all independent global loads (max MLP before math).
        const float4 yv  = *(const float4*)(y + (size_t)z * 4);
        const float4 x0v = *(const float4*)(xr + u);
        const float4 xa  = *(const float4*)(xr + 256 + u * 3);
        const float4 xb  = *(const float4*)(xr + 256 + u * 3 + 4);
        const float4 xc  = *(const float4*)(xr + 256 + u * 3 + 8);

        const float y0 = yv.x, e1x = yv.y, e1y = yv.z, e1z = yv.w;

        // unpack x1 vectors for the 4 u's
        const float vx[4]  = {xa.x, xa.w, xb.z, xc.y};
        const float vy[4]  = {xa.y, xb.x, xb.w, xc.z};
        const float vz[4]  = {xa.z, xb.y, xc.x, xc.w};
        const float x0s[4] = {x0v.x, x0v.y, x0v.z, x0v.w};

        float o0[4], ox[4], oy[4], oz[4];
        #pragma unroll
        for (int j = 0; j < 4; ++j) {
            const float dot = vx[j] * e1x + vy[j] * e1y + vz[j] * e1z;
            o0[j] = a0[j] * x0s[j] * y0 + a1[j] * dot;

            const float cx = vy[j] * e1z - vz[j] * e1y;
            const float cy = vz[j] * e1x - vx[j] * e1z;
            const float cz = vx[j] * e1y - vy[j] * e1x;

            const float s2 = a2[j] * x0s[j];   // scales y1
            const float s3 = a3[j] * y0;       // scales x1

            ox[j] = s2 * e1x + s3 * vx[j] + a4[j] * cx;
            oy[j] = s2 * e1y + s3 * vy[j] + a4[j] * cy;
            oz[j] = s2 * e1z + s3 * vz[j] + a4[j] * cz;
        }

        // stores: same layout as input
        *(float4*)(orow + u) = make_float4(o0[0], o0[1], o0[2], o0[3]);
        *(float4*)(orow + 256 + u * 3)     = make_float4(ox[0], oy[0], oz[0], ox[1]);
        *(float4*)(orow + 256 + u * 3 + 4) = make_float4(oy[1], oz[1], ox[2], oy[2]);
        *(float4*)(orow + 256 + u * 3 + 8) = make_float4(oz[2], ox[3], oy[3], oz[3]);
    }
}

extern "C" void kernel_launch(void* const* d_in, const int* in_sizes, int n_in,
                              void* d_out, int out_size)
{
    const float* x = (const float*)d_in[0];
    const float* y = (const float*)d_in[1];
    const float* w = (const float*)d_in[2];
    float* out = (float*)d_out;

    const int B = in_sizes[0] / 1024;
    const int grid = (B + ZPB - 1) / ZPB;
    tp_uvu_kernel<<<grid, THREADS>>>(x, y, w, out, B);
}